// round 2
// baseline (speedup 1.0000x reference)
#include <cuda_runtime.h>
#include <math.h>

#define BB 2
#define CC 128
#define NXY 4096
#define NN 8192            // nodes per batch (x then y)
#define KTOT 12
#define MROWS (BB*NN)      // 16384

// ---------------- scratch (device globals; no allocation allowed) -------------
__device__ float g_feat[MROWS*CC];   // 8 MB  [b][node][c]
__device__ float g_rel [MROWS*CC];   // 8 MB
__device__ float g_out [MROWS*CC];   // 8 MB
__device__ float g_norm[MROWS];
__device__ int   g_nbr [MROWS*KTOT];
__device__ float g_sum[CC];
__device__ float g_sumsq[CC];

// ---------------- 1) transpose inputs [B,C,N] -> feat [B,N,C] ----------------
__global__ void build_feat(const float* __restrict__ x, const float* __restrict__ y) {
    const int b = blockIdx.z, part = blockIdx.y;
    const int n0 = blockIdx.x * 32;
    const float* src = part ? y : x;            // [B][C][NXY]
    __shared__ float s[CC * 33];
    const int t = threadIdx.x;
#pragma unroll
    for (int p = 0; p < 16; ++p) {
        int c  = p * 8 + (t >> 5);
        int nn = t & 31;
        s[c * 33 + nn] = src[(size_t)(b * CC + c) * NXY + n0 + nn];
    }
    __syncthreads();
    const int nodeb = part * NXY + n0;
#pragma unroll
    for (int p = 0; p < 16; ++p) {
        int nn = p * 2 + (t >> 7);
        int c  = t & 127;
        g_feat[(size_t)(b * NN + nodeb + nn) * CC + c] = s[c * 33 + nn];
    }
}

// ---------------- 2) per-node squared norms ----------------------------------
__global__ void calc_norm() {
    const int node = blockIdx.x * 8 + (threadIdx.x >> 5);
    const int lane = threadIdx.x & 31;
    const float* f = g_feat + (size_t)node * CC;
    float s = 0.f;
#pragma unroll
    for (int i = 0; i < 4; ++i) { float v = f[lane + 32 * i]; s += v * v; }
#pragma unroll
    for (int o = 16; o; o >>= 1) s += __shfl_down_sync(0xffffffffu, s, o);
    if (!lane) g_norm[node] = s;
}

// ---------------- 3) fused distance-GEMM + streaming top-K -------------------
// Ranking score: ||c||^2 - 2*<q,c>  (query-norm term is rank-invariant).
// grid: (NXY/64, B, 2).  K=9: z=0 x->x, z=1 y->y (slot 0).
//                        K=3: z=0 x->y, z=1 y->x (slot 9).
template<int K>
__global__ void __launch_bounds__(256) knn_kernel() {
    const int b = blockIdx.y, z = blockIdx.z;
    int qb, cb, slot;
    if (K == 9) { qb = z ? NXY : 0; cb = qb;          slot = 0; }
    else        { qb = z ? NXY : 0; cb = z ? 0 : NXY; slot = 9; }
    const int q0 = blockIdx.x * 64;
    const int t  = threadIdx.x;

    __shared__ float sQ[64 * 33];
    __shared__ float sC[64 * 33];
    __shared__ float sD[64 * 65];
    __shared__ float sNrm[64];
    __shared__ int   sMI[64 * 2 * K];

    const float* fb = g_feat + (size_t)b * NN * CC;
    const float* nr = g_norm + b * NN;

    float ld[K]; int li[K];
#pragma unroll
    for (int u = 0; u < K; ++u) { ld[u] = 3.4e38f; li[u] = 0; }

    const int gy = t >> 4;     // 0..15  -> queries  gy + 16*i
    const int gx = t & 15;     //        -> cands    gx + 16*j
    float acc[4][4];

    for (int j0 = 0; j0 < NXY; j0 += 64) {
        if (t < 64) sNrm[t] = nr[cb + j0 + t];
#pragma unroll
        for (int i = 0; i < 4; ++i)
#pragma unroll
            for (int j = 0; j < 4; ++j) acc[i][j] = 0.f;

        for (int kc = 0; kc < CC; kc += 32) {
            __syncthreads();
#pragma unroll
            for (int u = 0; u < 8; ++u) {
                int e = t + 256 * u;
                int row = e >> 5, k = e & 31;
                sQ[row * 33 + k] = fb[(size_t)(qb + q0 + row) * CC + kc + k];
                sC[row * 33 + k] = fb[(size_t)(cb + j0 + row) * CC + kc + k];
            }
            __syncthreads();
#pragma unroll
            for (int k = 0; k < 32; ++k) {
                float a[4], c[4];
#pragma unroll
                for (int i = 0; i < 4; ++i) a[i] = sQ[(gy + 16 * i) * 33 + k];
#pragma unroll
                for (int j = 0; j < 4; ++j) c[j] = sC[(gx + 16 * j) * 33 + k];
#pragma unroll
                for (int i = 0; i < 4; ++i)
#pragma unroll
                    for (int j = 0; j < 4; ++j) acc[i][j] += a[i] * c[j];
            }
        }
        __syncthreads();
#pragma unroll
        for (int i = 0; i < 4; ++i)
#pragma unroll
            for (int j = 0; j < 4; ++j)
                sD[(gy + 16 * i) * 65 + gx + 16 * j] = sNrm[gx + 16 * j] - 2.f * acc[i][j];
        __syncthreads();
        // streaming top-K update: 128 scanners, each owns (query, half-row)
        if (t < 128) {
            const int q = t & 63, ch = t >> 6;
            const float* row = sD + q * 65 + ch * 32;
#pragma unroll
            for (int jj = 0; jj < 32; ++jj) {
                float s = row[jj];
                if (s < ld[K - 1]) {
                    int jidx = j0 + ch * 32 + jj;
                    int p = K - 1;
#pragma unroll
                    for (int u = K - 2; u >= 0; --u)
                        if (s < ld[u]) { ld[u + 1] = ld[u]; li[u + 1] = li[u]; p = u; }
                    ld[p] = s; li[p] = jidx;
                }
            }
        }
        __syncthreads();
    }
    // merge two partial lists per query
    float* sMD = sD;
    if (t < 128) {
        const int q = t & 63, ch = t >> 6;
#pragma unroll
        for (int u = 0; u < K; ++u) {
            sMD[(q * 2 + ch) * K + u] = ld[u];
            sMI[(q * 2 + ch) * K + u] = li[u];
        }
    }
    __syncthreads();
    if (t < 64) {
        float d[2 * K]; int ix[2 * K];
#pragma unroll
        for (int u = 0; u < 2 * K; ++u) { d[u] = sMD[t * 2 * K + u]; ix[u] = sMI[t * 2 * K + u]; }
        int* dst = g_nbr + (size_t)(b * NN + qb + q0 + t) * KTOT + slot;
        unsigned used = 0;
#pragma unroll
        for (int m = 0; m < K; ++m) {
            float bd = 3.5e38f; int best = 0;
#pragma unroll
            for (int u = 0; u < 2 * K; ++u)
                if (!((used >> u) & 1u) && d[u] < bd) { bd = d[u]; best = u; }
            used |= 1u << best;
            dst[m] = cb + ix[best];
        }
    }
}

// ---------------- 4) max-relative gather -------------------------------------
__global__ void rel_kernel() {
    const int r = blockIdx.x;           // 0..MROWS-1
    const int b = r >> 13;              // NN = 8192
    const int c = threadIdx.x;
    const int* nb = g_nbr + (size_t)r * KTOT;
    const float* fb = g_feat + (size_t)b * NN * CC;
    float m = -3.4e38f;
#pragma unroll
    for (int k = 0; k < KTOT; ++k) {
        int j = nb[k];
        m = fmaxf(m, fb[(size_t)j * CC + c]);
    }
    g_rel[(size_t)r * CC + c] = m - g_feat[(size_t)r * CC + c];
}

// ---------------- 5) 1x1 conv: out = [feat|rel] @ W[l]^T + b -----------------
__global__ void __launch_bounds__(256) conv_kernel(const float* __restrict__ W,
                                                   const float* __restrict__ bias, int l) {
    const int r0 = blockIdx.x * 64;
    const int t = threadIdx.x;
    const int ty = t >> 5, tx = t & 31;
    __shared__ float sH[64 * 33];
    __shared__ float sW[32 * 129];
    const float* Wl = W + (size_t)l * CC * 2 * CC;
    float acc[8][4];
#pragma unroll
    for (int i = 0; i < 8; ++i)
#pragma unroll
        for (int j = 0; j < 4; ++j) acc[i][j] = 0.f;

    for (int kc = 0; kc < 2 * CC; kc += 32) {
        __syncthreads();
        const float* src = kc < CC ? g_feat : g_rel;
        const int ko = kc < CC ? kc : kc - CC;
#pragma unroll
        for (int u = 0; u < 8; ++u) {
            int e = t + 256 * u; int row = e >> 5, k = e & 31;
            sH[row * 33 + k] = src[(size_t)(r0 + row) * CC + ko + k];
        }
#pragma unroll
        for (int u = 0; u < 16; ++u) {
            int e = t + 256 * u; int c = e >> 5, k = e & 31;
            sW[k * 129 + c] = Wl[(size_t)c * 2 * CC + kc + k];
        }
        __syncthreads();
#pragma unroll
        for (int k = 0; k < 32; ++k) {
            float a[8], w[4];
#pragma unroll
            for (int i = 0; i < 8; ++i) a[i] = sH[(ty + 8 * i) * 33 + k];
#pragma unroll
            for (int j = 0; j < 4; ++j) w[j] = sW[k * 129 + tx + 32 * j];
#pragma unroll
            for (int i = 0; i < 8; ++i)
#pragma unroll
                for (int j = 0; j < 4; ++j) acc[i][j] += a[i] * w[j];
        }
    }
#pragma unroll
    for (int j = 0; j < 4; ++j) {
        int c = tx + 32 * j;
        float bv = bias[l * CC + c];
#pragma unroll
        for (int i = 0; i < 8; ++i)
            g_out[(size_t)(r0 + ty + 8 * i) * CC + c] = acc[i][j] + bv;
    }
}

// ---------------- 6) batchnorm stats -----------------------------------------
__global__ void zero_stats() {
    int t = threadIdx.x;
    if (t < CC) { g_sum[t] = 0.f; g_sumsq[t] = 0.f; }
}

__global__ void stats_kernel() {
    const int r0 = blockIdx.x * 128;
    const int t = threadIdx.x;
    const int c = t & 127, half = t >> 7;
    float s = 0.f, ss = 0.f;
#pragma unroll 4
    for (int i = 0; i < 64; ++i) {
        float v = g_out[(size_t)(r0 + half + 2 * i) * CC + c];
        s += v; ss += v * v;
    }
    __shared__ float aS[256], aSS[256];
    aS[t] = s; aSS[t] = ss;
    __syncthreads();
    if (t < 128) {
        atomicAdd(&g_sum[c],   aS[t] + aS[t + 128]);
        atomicAdd(&g_sumsq[c], aSS[t] + aSS[t + 128]);
    }
}

// ---------------- 7) BN + tanh-GELU + residual (in place on feat) ------------
__global__ void bn_apply(const float* __restrict__ gamma, const float* __restrict__ beta, int l) {
    const int i = blockIdx.x * 256 + threadIdx.x;   // MROWS*CC elems exactly
    const int c = i & 127;
    const float inv_n = 1.f / (float)MROWS;
    float mean = g_sum[c] * inv_n;
    float var  = g_sumsq[c] * inv_n - mean * mean;
    float sc = rsqrtf(var + 1e-5f) * gamma[l * CC + c];
    float v = (g_out[i] - mean) * sc + beta[l * CC + c];
    float g = 0.5f * v * (1.f + tanhf(0.7978845608f * (v + 0.044715f * v * v * v)));
    g_feat[i] += g;
}

// ---------------- 8) transpose feat -> output [B,C,NX,1] ++ [B,C,NY,1] -------
__global__ void write_out(float* __restrict__ out) {
    const int b = blockIdx.z, part = blockIdx.y;
    const int n0 = blockIdx.x * 32;
    const int t = threadIdx.x;
    __shared__ float s[32 * 129];
#pragma unroll
    for (int p = 0; p < 16; ++p) {
        int nn = p * 2 + (t >> 7), c = t & 127;
        s[nn * 129 + c] = g_feat[(size_t)(b * NN + part * NXY + n0 + nn) * CC + c];
    }
    __syncthreads();
    float* dst = out + (size_t)part * BB * CC * NXY;
#pragma unroll
    for (int p = 0; p < 16; ++p) {
        int c = p * 8 + (t >> 5), nn = t & 31;
        dst[(size_t)(b * CC + c) * NXY + n0 + nn] = s[nn * 129 + c];
    }
}

// ---------------- launch ------------------------------------------------------
extern "C" void kernel_launch(void* const* d_in, const int* in_sizes, int n_in,
                              void* d_out, int out_size) {
    const float* x     = (const float*)d_in[0];
    const float* y     = (const float*)d_in[1];
    const float* W     = (const float*)d_in[2];
    const float* bias  = (const float*)d_in[3];
    const float* gamma = (const float*)d_in[4];
    const float* beta  = (const float*)d_in[5];

    build_feat<<<dim3(NXY / 32, 2, BB), 256>>>(x, y);
    calc_norm<<<MROWS / 8, 256>>>();
    knn_kernel<9><<<dim3(NXY / 64, BB, 2), 256>>>();
    knn_kernel<3><<<dim3(NXY / 64, BB, 2), 256>>>();

    for (int l = 0; l < 2; ++l) {
        rel_kernel<<<MROWS, 128>>>();
        conv_kernel<<<MROWS / 64, 256>>>(W, bias, l);
        zero_stats<<<1, 128>>>();
        stats_kernel<<<128, 256>>>();
        bn_apply<<<MROWS * CC / 256, 256>>>(gamma, beta, l);
    }

    write_out<<<dim3(NXY / 32, 2, BB), 256>>>((float*)d_out);
}

// round 3
// speedup vs baseline: 1.0876x; 1.0876x over previous
#include <cuda_runtime.h>
#include <math.h>

#define BB 2
#define CC 128
#define NXY 4096
#define NN 8192            // nodes per batch (x then y)
#define KTOT 12
#define MROWS (BB*NN)      // 16384

// ---------------- scratch (device globals; no allocation allowed) -------------
__device__ float g_feat[MROWS*CC];   // 8 MB  [b][node][c]
__device__ float g_rel [MROWS*CC];   // 8 MB
__device__ float g_out [MROWS*CC];   // 8 MB
__device__ float g_norm[MROWS];
__device__ int   g_nbr [MROWS*KTOT];
__device__ float g_sum[CC];
__device__ float g_sumsq[CC];

// ---------------- 1) transpose inputs [B,C,N] -> feat [B,N,C] ----------------
__global__ void build_feat(const float* __restrict__ x, const float* __restrict__ y) {
    const int b = blockIdx.z, part = blockIdx.y;
    const int n0 = blockIdx.x * 32;
    const float* src = part ? y : x;            // [B][C][NXY]
    __shared__ float s[CC * 33];
    const int t = threadIdx.x;
#pragma unroll
    for (int p = 0; p < 16; ++p) {
        int c  = p * 8 + (t >> 5);
        int nn = t & 31;
        s[c * 33 + nn] = src[(size_t)(b * CC + c) * NXY + n0 + nn];
    }
    __syncthreads();
    const int nodeb = part * NXY + n0;
#pragma unroll
    for (int p = 0; p < 16; ++p) {
        int nn = p * 2 + (t >> 7);
        int c  = t & 127;
        g_feat[(size_t)(b * NN + nodeb + nn) * CC + c] = s[c * 33 + nn];
    }
}

// ---------------- 2) per-node squared norms ----------------------------------
__global__ void calc_norm() {
    const int node = blockIdx.x * 8 + (threadIdx.x >> 5);
    const int lane = threadIdx.x & 31;
    const float* f = g_feat + (size_t)node * CC;
    float s = 0.f;
#pragma unroll
    for (int i = 0; i < 4; ++i) { float v = f[lane + 32 * i]; s += v * v; }
#pragma unroll
    for (int o = 16; o; o >>= 1) s += __shfl_down_sync(0xffffffffu, s, o);
    if (!lane) g_norm[node] = s;
}

// ---------------- 3) fused distance-GEMM + streaming top-K, ALL 4 modes ------
// Ranking score: ||c||^2 - 2*<q,c>  (query-norm term is rank-invariant).
// grid: (NXY/64, 4, B). mode 0: x->x (K9,slot0)  1: y->y (K9,slot0)
//                       mode 2: x->y (K3,slot9)  3: y->x (K3,slot9)
// Block tile: 64 queries x 128 candidates per j0 step, 256 threads,
// 4q x 8c micro-tile per thread, k-major smem with float4 LDS.
__global__ void __launch_bounds__(256) knn_all() {
    const int b = blockIdx.z, mode = blockIdx.y;
    const int qb = (mode & 1) ? NXY : 0;
    const int cb = ((mode + 1) & 2) ? NXY : 0;
    const int slot = (mode < 2) ? 0 : 9;
    const int KW = (mode < 2) ? 9 : 3;
    const int q0 = blockIdx.x * 64;
    const int t  = threadIdx.x;
    const int tx = t & 15, ty = t >> 4;

    __shared__ float sQ[32 * 68];     // [k][query]  (k-chunk of 32)
    __shared__ float sC[32 * 132];    // [k][cand]   (128 cands)
    __shared__ float sD[64 * 68];     // [query][cand-half 64] score staging
    __shared__ float sNrm[128];
    __shared__ int   sMI[64 * 2 * 9];

    const float* fb = g_feat + (size_t)b * NN * CC;
    const float* nr = g_norm + b * NN;

    float ld[9]; int li[9];
#pragma unroll
    for (int u = 0; u < 9; ++u) { ld[u] = 3.4e38f; li[u] = 0; }

    float acc[2][4][4];

    for (int j0 = 0; j0 < NXY; j0 += 128) {
        if (t < 128) sNrm[t] = nr[cb + j0 + t];
#pragma unroll
        for (int jj = 0; jj < 2; ++jj)
#pragma unroll
            for (int i = 0; i < 4; ++i)
#pragma unroll
                for (int v = 0; v < 4; ++v) acc[jj][i][v] = 0.f;

        for (int kc = 0; kc < CC; kc += 32) {
            __syncthreads();
#pragma unroll
            for (int u = 0; u < 2; ++u) {          // fill sQ (64q x 32k)
                int e = t + 256 * u;
                int q = e >> 3, kg = e & 7;
                float4 v4 = *(const float4*)&fb[(size_t)(qb + q0 + q) * CC + kc + kg * 4];
                sQ[(kg * 4 + 0) * 68 + q] = v4.x;
                sQ[(kg * 4 + 1) * 68 + q] = v4.y;
                sQ[(kg * 4 + 2) * 68 + q] = v4.z;
                sQ[(kg * 4 + 3) * 68 + q] = v4.w;
            }
#pragma unroll
            for (int u = 0; u < 4; ++u) {          // fill sC (128c x 32k)
                int e = t + 256 * u;
                int r = e >> 3, kg = e & 7;
                float4 v4 = *(const float4*)&fb[(size_t)(cb + j0 + r) * CC + kc + kg * 4];
                sC[(kg * 4 + 0) * 132 + r] = v4.x;
                sC[(kg * 4 + 1) * 132 + r] = v4.y;
                sC[(kg * 4 + 2) * 132 + r] = v4.z;
                sC[(kg * 4 + 3) * 132 + r] = v4.w;
            }
            __syncthreads();
#pragma unroll
            for (int k = 0; k < 32; ++k) {
                float4 a4 = *(const float4*)(sQ + k * 68 + ty * 4);
                float4 c0 = *(const float4*)(sC + k * 132 + tx * 4);
                float4 c1 = *(const float4*)(sC + k * 132 + 64 + tx * 4);
                float av[4] = {a4.x, a4.y, a4.z, a4.w};
                float v0[4] = {c0.x, c0.y, c0.z, c0.w};
                float v1[4] = {c1.x, c1.y, c1.z, c1.w};
#pragma unroll
                for (int i = 0; i < 4; ++i)
#pragma unroll
                    for (int v = 0; v < 4; ++v) {
                        acc[0][i][v] += av[i] * v0[v];
                        acc[1][i][v] += av[i] * v1[v];
                    }
            }
        }
        // stage scores + scan, one 64-cand half at a time
#pragma unroll
        for (int jj = 0; jj < 2; ++jj) {
            __syncthreads();
#pragma unroll
            for (int i = 0; i < 4; ++i) {
                float4 s;
                s.x = sNrm[jj * 64 + tx * 4 + 0] - 2.f * acc[jj][i][0];
                s.y = sNrm[jj * 64 + tx * 4 + 1] - 2.f * acc[jj][i][1];
                s.z = sNrm[jj * 64 + tx * 4 + 2] - 2.f * acc[jj][i][2];
                s.w = sNrm[jj * 64 + tx * 4 + 3] - 2.f * acc[jj][i][3];
                *(float4*)(sD + (ty * 4 + i) * 68 + tx * 4) = s;
            }
            __syncthreads();
            if (t < 128) {
                const int q = t & 63, ch = t >> 6;
                const float* row = sD + q * 68 + ch * 32;
                const int cbase = j0 + jj * 64 + ch * 32;
#pragma unroll
                for (int m = 0; m < 32; ++m) {
                    float s = row[m];
                    if (s < ld[8]) {
                        int jidx = cbase + m;
                        int p = 8;
#pragma unroll
                        for (int u = 7; u >= 0; --u)
                            if (s < ld[u]) { ld[u + 1] = ld[u]; li[u + 1] = li[u]; p = u; }
                        ld[p] = s; li[p] = jidx;
                    }
                }
            }
        }
    }
    // merge two partial lists per query
    __syncthreads();
    if (t < 128) {
        const int q = t & 63, ch = t >> 6;
#pragma unroll
        for (int u = 0; u < 9; ++u) {
            sD[(q * 2 + ch) * 9 + u]  = ld[u];
            sMI[(q * 2 + ch) * 9 + u] = li[u];
        }
    }
    __syncthreads();
    if (t < 64) {
        float d[18]; int ix[18];
#pragma unroll
        for (int u = 0; u < 18; ++u) { d[u] = sD[t * 18 + u]; ix[u] = sMI[t * 18 + u]; }
        int* dst = g_nbr + (size_t)(b * NN + qb + q0 + t) * KTOT + slot;
        unsigned used = 0;
        for (int m = 0; m < KW; ++m) {
            float bd = 3.5e38f; int best = 0;
#pragma unroll
            for (int u = 0; u < 18; ++u)
                if (!((used >> u) & 1u) && d[u] < bd) { bd = d[u]; best = u; }
            used |= 1u << best;
            dst[m] = cb + ix[best];
        }
    }
}

// ---------------- 4) max-relative gather -------------------------------------
__global__ void rel_kernel() {
    const int r = blockIdx.x;           // 0..MROWS-1
    const int b = r >> 13;              // NN = 8192
    const int c = threadIdx.x;
    const int* nb = g_nbr + (size_t)r * KTOT;
    const float* fb = g_feat + (size_t)b * NN * CC;
    float m = -3.4e38f;
#pragma unroll
    for (int k = 0; k < KTOT; ++k) {
        int j = nb[k];
        m = fmaxf(m, fb[(size_t)j * CC + c]);
    }
    g_rel[(size_t)r * CC + c] = m - g_feat[(size_t)r * CC + c];
}

// ---------------- 5) 1x1 conv: out = [feat|rel] @ W[l]^T + b -----------------
__global__ void __launch_bounds__(256) conv_kernel(const float* __restrict__ W,
                                                   const float* __restrict__ bias, int l) {
    const int r0 = blockIdx.x * 64;
    const int t = threadIdx.x;
    const int ty = t >> 5, tx = t & 31;
    __shared__ float sH[64 * 33];
    __shared__ float sW[32 * 129];
    const float* Wl = W + (size_t)l * CC * 2 * CC;
    float acc[8][4];
#pragma unroll
    for (int i = 0; i < 8; ++i)
#pragma unroll
        for (int j = 0; j < 4; ++j) acc[i][j] = 0.f;

    for (int kc = 0; kc < 2 * CC; kc += 32) {
        __syncthreads();
        const float* src = kc < CC ? g_feat : g_rel;
        const int ko = kc < CC ? kc : kc - CC;
#pragma unroll
        for (int u = 0; u < 8; ++u) {
            int e = t + 256 * u; int row = e >> 5, k = e & 31;
            sH[row * 33 + k] = src[(size_t)(r0 + row) * CC + ko + k];
        }
#pragma unroll
        for (int u = 0; u < 16; ++u) {
            int e = t + 256 * u; int c = e >> 5, k = e & 31;
            sW[k * 129 + c] = Wl[(size_t)c * 2 * CC + kc + k];
        }
        __syncthreads();
#pragma unroll
        for (int k = 0; k < 32; ++k) {
            float a[8], w[4];
#pragma unroll
            for (int i = 0; i < 8; ++i) a[i] = sH[(ty + 8 * i) * 33 + k];
#pragma unroll
            for (int j = 0; j < 4; ++j) w[j] = sW[k * 129 + tx + 32 * j];
#pragma unroll
            for (int i = 0; i < 8; ++i)
#pragma unroll
                for (int j = 0; j < 4; ++j) acc[i][j] += a[i] * w[j];
        }
    }
#pragma unroll
    for (int j = 0; j < 4; ++j) {
        int c = tx + 32 * j;
        float bv = bias[l * CC + c];
#pragma unroll
        for (int i = 0; i < 8; ++i)
            g_out[(size_t)(r0 + ty + 8 * i) * CC + c] = acc[i][j] + bv;
    }
}

// ---------------- 6) batchnorm stats -----------------------------------------
__global__ void zero_stats() {
    int t = threadIdx.x;
    if (t < CC) { g_sum[t] = 0.f; g_sumsq[t] = 0.f; }
}

__global__ void stats_kernel() {
    const int r0 = blockIdx.x * 128;
    const int t = threadIdx.x;
    const int c = t & 127, half = t >> 7;
    float s = 0.f, ss = 0.f;
#pragma unroll 4
    for (int i = 0; i < 64; ++i) {
        float v = g_out[(size_t)(r0 + half + 2 * i) * CC + c];
        s += v; ss += v * v;
    }
    __shared__ float aS[256], aSS[256];
    aS[t] = s; aSS[t] = ss;
    __syncthreads();
    if (t < 128) {
        atomicAdd(&g_sum[c],   aS[t] + aS[t + 128]);
        atomicAdd(&g_sumsq[c], aSS[t] + aSS[t + 128]);
    }
}

// ---------------- 7) BN + tanh-GELU + residual (in place on feat) ------------
__global__ void bn_apply(const float* __restrict__ gamma, const float* __restrict__ beta, int l) {
    const int i = blockIdx.x * 256 + threadIdx.x;   // MROWS*CC elems exactly
    const int c = i & 127;
    const float inv_n = 1.f / (float)MROWS;
    float mean = g_sum[c] * inv_n;
    float var  = g_sumsq[c] * inv_n - mean * mean;
    float sc = rsqrtf(var + 1e-5f) * gamma[l * CC + c];
    float v = (g_out[i] - mean) * sc + beta[l * CC + c];
    float g = 0.5f * v * (1.f + tanhf(0.7978845608f * (v + 0.044715f * v * v * v)));
    g_feat[i] += g;
}

// ---------------- 8) transpose feat -> output [B,C,NX,1] ++ [B,C,NY,1] -------
__global__ void write_out(float* __restrict__ out) {
    const int b = blockIdx.z, part = blockIdx.y;
    const int n0 = blockIdx.x * 32;
    const int t = threadIdx.x;
    __shared__ float s[32 * 129];
#pragma unroll
    for (int p = 0; p < 16; ++p) {
        int nn = p * 2 + (t >> 7), c = t & 127;
        s[nn * 129 + c] = g_feat[(size_t)(b * NN + part * NXY + n0 + nn) * CC + c];
    }
    __syncthreads();
    float* dst = out + (size_t)part * BB * CC * NXY;
#pragma unroll
    for (int p = 0; p < 16; ++p) {
        int c = p * 8 + (t >> 5), nn = t & 31;
        dst[(size_t)(b * CC + c) * NXY + n0 + nn] = s[nn * 129 + c];
    }
}

// ---------------- launch ------------------------------------------------------
extern "C" void kernel_launch(void* const* d_in, const int* in_sizes, int n_in,
                              void* d_out, int out_size) {
    const float* x     = (const float*)d_in[0];
    const float* y     = (const float*)d_in[1];
    const float* W     = (const float*)d_in[2];
    const float* bias  = (const float*)d_in[3];
    const float* gamma = (const float*)d_in[4];
    const float* beta  = (const float*)d_in[5];

    build_feat<<<dim3(NXY / 32, 2, BB), 256>>>(x, y);
    calc_norm<<<MROWS / 8, 256>>>();
    knn_all<<<dim3(NXY / 64, 4, BB), 256>>>();

    for (int l = 0; l < 2; ++l) {
        rel_kernel<<<MROWS, 128>>>();
        conv_kernel<<<MROWS / 64, 256>>>(W, bias, l);
        zero_stats<<<1, 128>>>();
        stats_kernel<<<128, 256>>>();
        bn_apply<<<MROWS * CC / 256, 256>>>(gamma, beta, l);
    }

    write_out<<<dim3(NXY / 32, 2, BB), 256>>>((float*)d_out);
}

// round 4
// speedup vs baseline: 1.2779x; 1.1750x over previous
#include <cuda_runtime.h>
#include <math.h>

#define BB 2
#define CC 128
#define NXY 4096
#define NN 8192            // nodes per batch (x then y)
#define KTOT 12
#define MROWS (BB*NN)      // 16384

typedef unsigned long long u64;

// packed fp32x2 helpers (Blackwell f32x2 pipe; only reachable via PTX)
__device__ __forceinline__ void fma2(u64& acc, u64 a, u64 b) {
    asm("fma.rn.f32x2 %0, %1, %2, %0;" : "+l"(acc) : "l"(a), "l"(b));
}
__device__ __forceinline__ u64 pk2(float x) {
    u64 r; asm("mov.b64 %0, {%1, %1};" : "=l"(r) : "f"(x)); return r;
}
__device__ __forceinline__ u64 pk2p(float x, float y) {
    u64 r; asm("mov.b64 %0, {%1, %2};" : "=l"(r) : "f"(x), "f"(y)); return r;
}
__device__ __forceinline__ float2 upk(u64 p) {
    float2 r; asm("mov.b64 {%0, %1}, %2;" : "=f"(r.x), "=f"(r.y) : "l"(p)); return r;
}

// ---------------- scratch (device globals; no allocation allowed) -------------
__device__ float g_feat[MROWS*CC];   // 8 MB  [b][node][c]
__device__ float g_rel [MROWS*CC];   // 8 MB
__device__ float g_out [MROWS*CC];   // 8 MB
__device__ float g_norm[MROWS];
__device__ int   g_nbr [MROWS*KTOT];
__device__ float g_sum[CC];
__device__ float g_sumsq[CC];

// ---------------- 1) transpose inputs [B,C,N] -> feat [B,N,C] ----------------
__global__ void build_feat(const float* __restrict__ x, const float* __restrict__ y) {
    const int b = blockIdx.z, part = blockIdx.y;
    const int n0 = blockIdx.x * 32;
    const float* src = part ? y : x;            // [B][C][NXY]
    __shared__ float s[CC * 33];
    const int t = threadIdx.x;
#pragma unroll
    for (int p = 0; p < 16; ++p) {
        int c  = p * 8 + (t >> 5);
        int nn = t & 31;
        s[c * 33 + nn] = src[(size_t)(b * CC + c) * NXY + n0 + nn];
    }
    __syncthreads();
    const int nodeb = part * NXY + n0;
#pragma unroll
    for (int p = 0; p < 16; ++p) {
        int nn = p * 2 + (t >> 7);
        int c  = t & 127;
        g_feat[(size_t)(b * NN + nodeb + nn) * CC + c] = s[c * 33 + nn];
    }
}

// ---------------- 2) per-node squared norms ----------------------------------
__global__ void calc_norm() {
    const int node = blockIdx.x * 8 + (threadIdx.x >> 5);
    const int lane = threadIdx.x & 31;
    const float* f = g_feat + (size_t)node * CC;
    float s = 0.f;
#pragma unroll
    for (int i = 0; i < 4; ++i) { float v = f[lane + 32 * i]; s += v * v; }
#pragma unroll
    for (int o = 16; o; o >>= 1) s += __shfl_down_sync(0xffffffffu, s, o);
    if (!lane) g_norm[node] = s;
}

// ---------------- 3) fused distance-GEMM + streaming top-K, ALL 4 modes ------
// Ranking score: ||c||^2 - 2*<q,c>  (query-norm term is rank-invariant).
// grid: (NXY/64, 4, B). mode 0: x->x (K9,slot0)  1: y->y (K9,slot0)
//                       mode 2: x->y (K3,slot9)  3: y->x (K3,slot9)
// 64 queries x 128 candidates per j0 step, 256 threads, 4q x 8c micro-tile,
// inner product via packed fp32x2 FMA (bit-identical to scalar fp32).
__global__ void __launch_bounds__(256) knn_all() {
    const int b = blockIdx.z, mode = blockIdx.y;
    const int qb = (mode & 1) ? NXY : 0;
    const int cb = ((mode + 1) & 2) ? NXY : 0;
    const int slot = (mode < 2) ? 0 : 9;
    const int KW = (mode < 2) ? 9 : 3;
    const int q0 = blockIdx.x * 64;
    const int t  = threadIdx.x;
    const int tx = t & 15, ty = t >> 4;

    __shared__ float sQ[32 * 68];     // [k][query]  (k-chunk of 32)
    __shared__ float sC[32 * 132];    // [k][cand]   (128 cands)
    __shared__ float sD[64 * 68];     // [query][cand-half 64] score staging
    __shared__ float sNrm[128];
    __shared__ int   sMI[64 * 2 * 9];

    const float* fb = g_feat + (size_t)b * NN * CC;
    const float* nr = g_norm + b * NN;

    float ld[9]; int li[9];
#pragma unroll
    for (int u = 0; u < 9; ++u) { ld[u] = 3.4e38f; li[u] = 0; }

    u64 acc2[2][4][2];                // [cand-half][query i][cand pair]

    for (int j0 = 0; j0 < NXY; j0 += 128) {
        if (t < 128) sNrm[t] = nr[cb + j0 + t];
#pragma unroll
        for (int jj = 0; jj < 2; ++jj)
#pragma unroll
            for (int i = 0; i < 4; ++i)
#pragma unroll
                for (int p = 0; p < 2; ++p) acc2[jj][i][p] = 0ull;

        for (int kc = 0; kc < CC; kc += 32) {
            __syncthreads();
#pragma unroll
            for (int u = 0; u < 2; ++u) {          // fill sQ (64q x 32k)
                int e = t + 256 * u;
                int q = e >> 3, kg = e & 7;
                float4 v4 = *(const float4*)&fb[(size_t)(qb + q0 + q) * CC + kc + kg * 4];
                sQ[(kg * 4 + 0) * 68 + q] = v4.x;
                sQ[(kg * 4 + 1) * 68 + q] = v4.y;
                sQ[(kg * 4 + 2) * 68 + q] = v4.z;
                sQ[(kg * 4 + 3) * 68 + q] = v4.w;
            }
#pragma unroll
            for (int u = 0; u < 4; ++u) {          // fill sC (128c x 32k)
                int e = t + 256 * u;
                int r = e >> 3, kg = e & 7;
                float4 v4 = *(const float4*)&fb[(size_t)(cb + j0 + r) * CC + kc + kg * 4];
                sC[(kg * 4 + 0) * 132 + r] = v4.x;
                sC[(kg * 4 + 1) * 132 + r] = v4.y;
                sC[(kg * 4 + 2) * 132 + r] = v4.z;
                sC[(kg * 4 + 3) * 132 + r] = v4.w;
            }
            __syncthreads();
#pragma unroll
            for (int k = 0; k < 32; ++k) {
                float4 a4 = *(const float4*)(sQ + k * 68 + ty * 4);
                u64 aa0 = pk2(a4.x), aa1 = pk2(a4.y), aa2 = pk2(a4.z), aa3 = pk2(a4.w);
                const float* cp = sC + k * 132;
                u64 c00 = *(const u64*)(cp + tx * 4);
                u64 c01 = *(const u64*)(cp + tx * 4 + 2);
                u64 c10 = *(const u64*)(cp + 64 + tx * 4);
                u64 c11 = *(const u64*)(cp + 64 + tx * 4 + 2);
                fma2(acc2[0][0][0], aa0, c00); fma2(acc2[0][0][1], aa0, c01);
                fma2(acc2[0][1][0], aa1, c00); fma2(acc2[0][1][1], aa1, c01);
                fma2(acc2[0][2][0], aa2, c00); fma2(acc2[0][2][1], aa2, c01);
                fma2(acc2[0][3][0], aa3, c00); fma2(acc2[0][3][1], aa3, c01);
                fma2(acc2[1][0][0], aa0, c10); fma2(acc2[1][0][1], aa0, c11);
                fma2(acc2[1][1][0], aa1, c10); fma2(acc2[1][1][1], aa1, c11);
                fma2(acc2[1][2][0], aa2, c10); fma2(acc2[1][2][1], aa2, c11);
                fma2(acc2[1][3][0], aa3, c10); fma2(acc2[1][3][1], aa3, c11);
            }
        }
        // stage scores + scan, one 64-cand half at a time
#pragma unroll
        for (int jj = 0; jj < 2; ++jj) {
            __syncthreads();
#pragma unroll
            for (int i = 0; i < 4; ++i) {
                float2 p0 = upk(acc2[jj][i][0]);
                float2 p1 = upk(acc2[jj][i][1]);
                float4 s;
                s.x = sNrm[jj * 64 + tx * 4 + 0] - 2.f * p0.x;
                s.y = sNrm[jj * 64 + tx * 4 + 1] - 2.f * p0.y;
                s.z = sNrm[jj * 64 + tx * 4 + 2] - 2.f * p1.x;
                s.w = sNrm[jj * 64 + tx * 4 + 3] - 2.f * p1.y;
                *(float4*)(sD + (ty * 4 + i) * 68 + tx * 4) = s;
            }
            __syncthreads();
            if (t < 128) {
                const int q = t & 63, ch = t >> 6;
                const float* row = sD + q * 68 + ch * 32;
                const int cbase = j0 + jj * 64 + ch * 32;
#pragma unroll
                for (int m = 0; m < 32; ++m) {
                    float s = row[m];
                    if (s < ld[8]) {
                        int jidx = cbase + m;
                        int p = 8;
#pragma unroll
                        for (int u = 7; u >= 0; --u)
                            if (s < ld[u]) { ld[u + 1] = ld[u]; li[u + 1] = li[u]; p = u; }
                        ld[p] = s; li[p] = jidx;
                    }
                }
            }
        }
    }
    // merge two partial lists per query
    __syncthreads();
    if (t < 128) {
        const int q = t & 63, ch = t >> 6;
#pragma unroll
        for (int u = 0; u < 9; ++u) {
            sD[(q * 2 + ch) * 9 + u]  = ld[u];
            sMI[(q * 2 + ch) * 9 + u] = li[u];
        }
    }
    __syncthreads();
    if (t < 64) {
        float d[18]; int ix[18];
#pragma unroll
        for (int u = 0; u < 18; ++u) { d[u] = sD[t * 18 + u]; ix[u] = sMI[t * 18 + u]; }
        int* dst = g_nbr + (size_t)(b * NN + qb + q0 + t) * KTOT + slot;
        unsigned used = 0;
        for (int m = 0; m < KW; ++m) {
            float bd = 3.5e38f; int best = 0;
#pragma unroll
            for (int u = 0; u < 18; ++u)
                if (!((used >> u) & 1u) && d[u] < bd) { bd = d[u]; best = u; }
            used |= 1u << best;
            dst[m] = cb + ix[best];
        }
    }
}

// ---------------- 4) max-relative gather -------------------------------------
__global__ void rel_kernel() {
    const int r = blockIdx.x;           // 0..MROWS-1
    const int b = r >> 13;              // NN = 8192
    const int c = threadIdx.x;
    const int* nb = g_nbr + (size_t)r * KTOT;
    const float* fb = g_feat + (size_t)b * NN * CC;
    float m = -3.4e38f;
#pragma unroll
    for (int k = 0; k < KTOT; ++k) {
        int j = nb[k];
        m = fmaxf(m, fb[(size_t)j * CC + c]);
    }
    g_rel[(size_t)r * CC + c] = m - g_feat[(size_t)r * CC + c];
}

// ---------------- 5) 1x1 conv: out = [feat|rel] @ W[l]^T + b -----------------
// 64 rows x 128 channels per block; each thread: 8 rows x 4 contiguous
// channels (tx*4..tx*4+3), packed fp32x2 accumulation.
__global__ void __launch_bounds__(256) conv_kernel(const float* __restrict__ W,
                                                   const float* __restrict__ bias, int l) {
    const int r0 = blockIdx.x * 64;
    const int t = threadIdx.x;
    const int ty = t >> 5, tx = t & 31;
    __shared__ float sH[64 * 33];
    __shared__ float sW[32 * 132];   // [k][channel]
    const float* Wl = W + (size_t)l * CC * 2 * CC;
    u64 acc2[8][2];
#pragma unroll
    for (int i = 0; i < 8; ++i) { acc2[i][0] = 0ull; acc2[i][1] = 0ull; }

    for (int kc = 0; kc < 2 * CC; kc += 32) {
        __syncthreads();
        const float* src = kc < CC ? g_feat : g_rel;
        const int ko = kc < CC ? kc : kc - CC;
#pragma unroll
        for (int u = 0; u < 8; ++u) {
            int e = t + 256 * u; int row = e >> 5, k = e & 31;
            sH[row * 33 + k] = src[(size_t)(r0 + row) * CC + ko + k];
        }
#pragma unroll
        for (int u = 0; u < 4; ++u) {          // 128c x 8 k-groups of 4
            int e = t + 256 * u;
            int c = e >> 3, kg = e & 7;
            float4 w4 = *(const float4*)&Wl[(size_t)c * 2 * CC + kc + kg * 4];
            sW[(kg * 4 + 0) * 132 + c] = w4.x;
            sW[(kg * 4 + 1) * 132 + c] = w4.y;
            sW[(kg * 4 + 2) * 132 + c] = w4.z;
            sW[(kg * 4 + 3) * 132 + c] = w4.w;
        }
        __syncthreads();
#pragma unroll
        for (int k = 0; k < 32; ++k) {
            float4 w4 = *(const float4*)(sW + k * 132 + tx * 4);
            u64 w0 = pk2p(w4.x, w4.y);
            u64 w1 = pk2p(w4.z, w4.w);
#pragma unroll
            for (int i = 0; i < 8; ++i) {
                u64 ap = pk2(sH[(ty + 8 * i) * 33 + k]);
                fma2(acc2[i][0], ap, w0);
                fma2(acc2[i][1], ap, w1);
            }
        }
    }
    float4 bv = *(const float4*)&bias[l * CC + tx * 4];
#pragma unroll
    for (int i = 0; i < 8; ++i) {
        float2 p0 = upk(acc2[i][0]);
        float2 p1 = upk(acc2[i][1]);
        float4 o; o.x = p0.x + bv.x; o.y = p0.y + bv.y; o.z = p1.x + bv.z; o.w = p1.y + bv.w;
        *(float4*)&g_out[(size_t)(r0 + ty + 8 * i) * CC + tx * 4] = o;
    }
}

// ---------------- 6) batchnorm stats -----------------------------------------
__global__ void zero_stats() {
    int t = threadIdx.x;
    if (t < CC) { g_sum[t] = 0.f; g_sumsq[t] = 0.f; }
}

__global__ void stats_kernel() {
    const int r0 = blockIdx.x * 128;
    const int t = threadIdx.x;
    const int c = t & 127, half = t >> 7;
    float s = 0.f, ss = 0.f;
#pragma unroll 4
    for (int i = 0; i < 64; ++i) {
        float v = g_out[(size_t)(r0 + half + 2 * i) * CC + c];
        s += v; ss += v * v;
    }
    __shared__ float aS[256], aSS[256];
    aS[t] = s; aSS[t] = ss;
    __syncthreads();
    if (t < 128) {
        atomicAdd(&g_sum[c],   aS[t] + aS[t + 128]);
        atomicAdd(&g_sumsq[c], aSS[t] + aSS[t + 128]);
    }
}

// ---------------- 7) BN + tanh-GELU + residual (in place on feat) ------------
__global__ void bn_apply(const float* __restrict__ gamma, const float* __restrict__ beta, int l) {
    const int i = blockIdx.x * 256 + threadIdx.x;   // MROWS*CC elems exactly
    const int c = i & 127;
    const float inv_n = 1.f / (float)MROWS;
    float mean = g_sum[c] * inv_n;
    float var  = g_sumsq[c] * inv_n - mean * mean;
    float sc = rsqrtf(var + 1e-5f) * gamma[l * CC + c];
    float v = (g_out[i] - mean) * sc + beta[l * CC + c];
    float g = 0.5f * v * (1.f + tanhf(0.7978845608f * (v + 0.044715f * v * v * v)));
    g_feat[i] += g;
}

// ---------------- 8) transpose feat -> output [B,C,NX,1] ++ [B,C,NY,1] -------
__global__ void write_out(float* __restrict__ out) {
    const int b = blockIdx.z, part = blockIdx.y;
    const int n0 = blockIdx.x * 32;
    const int t = threadIdx.x;
    __shared__ float s[32 * 129];
#pragma unroll
    for (int p = 0; p < 16; ++p) {
        int nn = p * 2 + (t >> 7), c = t & 127;
        s[nn * 129 + c] = g_feat[(size_t)(b * NN + part * NXY + n0 + nn) * CC + c];
    }
    __syncthreads();
    float* dst = out + (size_t)part * BB * CC * NXY;
#pragma unroll
    for (int p = 0; p < 16; ++p) {
        int c = p * 8 + (t >> 5), nn = t & 31;
        dst[(size_t)(b * CC + c) * NXY + n0 + nn] = s[nn * 129 + c];
    }
}

// ---------------- launch ------------------------------------------------------
extern "C" void kernel_launch(void* const* d_in, const int* in_sizes, int n_in,
                              void* d_out, int out_size) {
    const float* x     = (const float*)d_in[0];
    const float* y     = (const float*)d_in[1];
    const float* W     = (const float*)d_in[2];
    const float* bias  = (const float*)d_in[3];
    const float* gamma = (const float*)d_in[4];
    const float* beta  = (const float*)d_in[5];

    build_feat<<<dim3(NXY / 32, 2, BB), 256>>>(x, y);
    calc_norm<<<MROWS / 8, 256>>>();
    knn_all<<<dim3(NXY / 64, 4, BB), 256>>>();

    for (int l = 0; l < 2; ++l) {
        rel_kernel<<<MROWS, 128>>>();
        conv_kernel<<<MROWS / 64, 256>>>(W, bias, l);
        zero_stats<<<1, 128>>>();
        stats_kernel<<<128, 256>>>();
        bn_apply<<<MROWS * CC / 256, 256>>>(gamma, beta, l);
    }

    write_out<<<dim3(NXY / 32, 2, BB), 256>>>((float*)d_out);
}